// round 1
// baseline (speedup 1.0000x reference)
#include <cuda_runtime.h>
#include <math.h>

#define BB   4
#define NN   8192
#define CC   256
#define DD   256
#define LSEG 2048
#define NSEG 28

// ---------------- scratch (__device__ globals; no runtime alloc) ----------
__device__ float g_Q[BB * NN * DD];
__device__ float g_K[BB * NN * DD];
__device__ float g_V[BB * NN * DD];
__device__ float g_O[NSEG * LSEG * DD];
__device__ float g_den[NSEG * LSEG];

// ---------------- Phase 1: QKV projection GEMM ----------------------------
// X[32768,256] @ W[256,256] -> {Q,K,V}[32768,256].  grid=(512,4,3), 256 thr.
__global__ __launch_bounds__(256) void qkv_kernel(
    const float* __restrict__ X, const float* __restrict__ Wq,
    const float* __restrict__ Wk, const float* __restrict__ Wv)
{
    const float* W   = (blockIdx.z == 0) ? Wq : (blockIdx.z == 1) ? Wk : Wv;
    float*       Out = (blockIdx.z == 0) ? g_Q : (blockIdx.z == 1) ? g_K : g_V;
    const int m0 = blockIdx.x * 64, n0 = blockIdx.y * 64;

    __shared__ float Xs[64][33];
    __shared__ float Ws[32][68];

    const int t = threadIdx.x, tx = t & 15, ty = t >> 4;
    float acc[4][4];
#pragma unroll
    for (int i = 0; i < 4; i++)
#pragma unroll
        for (int j = 0; j < 4; j++) acc[i][j] = 0.f;

    for (int k0 = 0; k0 < CC; k0 += 32) {
#pragma unroll
        for (int v = 0; v < 2; v++) {            // 64x32 X tile (512 float4)
            int idx = t + v * 256;
            int row = idx >> 3, c4 = (idx & 7) << 2;
            float4 x4 = *(const float4*)(X + (long)(m0 + row) * CC + k0 + c4);
            Xs[row][c4] = x4.x; Xs[row][c4 + 1] = x4.y;
            Xs[row][c4 + 2] = x4.z; Xs[row][c4 + 3] = x4.w;
        }
#pragma unroll
        for (int v = 0; v < 2; v++) {            // 32x64 W tile
            int idx = t + v * 256;
            int row = idx >> 4, c4 = (idx & 15) << 2;
            float4 w4 = *(const float4*)(W + (long)(k0 + row) * DD + n0 + c4);
            Ws[row][c4] = w4.x; Ws[row][c4 + 1] = w4.y;
            Ws[row][c4 + 2] = w4.z; Ws[row][c4 + 3] = w4.w;
        }
        __syncthreads();
#pragma unroll 8
        for (int kk = 0; kk < 32; kk++) {
            float a[4], b[4];
#pragma unroll
            for (int i = 0; i < 4; i++) a[i] = Xs[ty + 16 * i][kk];
#pragma unroll
            for (int j = 0; j < 4; j++) b[j] = Ws[kk][tx + 16 * j];
#pragma unroll
            for (int i = 0; i < 4; i++)
#pragma unroll
                for (int j = 0; j < 4; j++) acc[i][j] = fmaf(a[i], b[j], acc[i][j]);
        }
        __syncthreads();
    }
#pragma unroll
    for (int i = 0; i < 4; i++)
#pragma unroll
        for (int j = 0; j < 4; j++)
            Out[(long)(m0 + ty + 16 * i) * DD + n0 + tx + 16 * j] = acc[i][j];
}

// ---------------- Phase 2: per-segment causal flash attention --------------
__device__ __forceinline__ float rmax16(float v) {
#pragma unroll
    for (int o = 8; o > 0; o >>= 1)
        v = fmaxf(v, __shfl_xor_sync(0xffffffffu, v, o, 16));
    return v;
}
__device__ __forceinline__ float rsum16(float v) {
#pragma unroll
    for (int o = 8; o > 0; o >>= 1)
        v += __shfl_xor_sync(0xffffffffu, v, o, 16);
    return v;
}

#define QS_STRIDE 258
#define PS_OFF    (64 * QS_STRIDE)          // 16512 floats
#define PS_STRIDE 65
#define KV_OFF    (PS_OFF + 64 * PS_STRIDE) // 20672 floats
#define SMEM_FLOATS (KV_OFF + 32 * 256)     // 28864 floats = 115456 B

// grid = (32 q-tiles, 28 segments), 256 threads, dyn smem 115456B
__global__ __launch_bounds__(256, 1) void attn_kernel()
{
    extern __shared__ float sm[];
    float* Qs  = sm;
    float* Ps  = sm + PS_OFF;
    float* KVs = sm + KV_OFF;

    const int qt = 31 - (int)blockIdx.x;   // heavy (causal-long) tiles first
    const int s  = blockIdx.y;
    int w, r, base;
    if (s < 16)      { w = 2048; r = 1; base = 0;  }
    else if (s < 24) { w = 4096; r = 2; base = 16; }
    else             { w = 8192; r = 4; base = 24; }
    const int local  = s - base;
    const int seg_id = local >> 2, batch = local & 3;
    const long qkvbase = (long)batch * (NN * DD);
    const int  posbase = seg_id * w;

    const int t = threadIdx.x, tx = t & 15, ty = t >> 4;

    // load 64x256 Q tile, pre-scaled by 1/sqrt(D)=1/16 (exact pow2)
#pragma unroll
    for (int v = 0; v < 16; v++) {
        int idx = t + v * 256;                   // 4096 float4
        int row = idx >> 6, c4 = (idx & 63) << 2;
        long g = qkvbase + (long)(posbase + (qt * 64 + row) * r) * DD + c4;
        float4 q4 = *(const float4*)(g_Q + g);
        float* qs = Qs + row * QS_STRIDE + c4;
        qs[0] = q4.x * 0.0625f; qs[1] = q4.y * 0.0625f;
        qs[2] = q4.z * 0.0625f; qs[3] = q4.w * 0.0625f;
    }

    float m_i[4], l_i[4], o_acc[4][16];
#pragma unroll
    for (int i = 0; i < 4; i++) {
        m_i[i] = -1e30f; l_i[i] = 0.f;
#pragma unroll
        for (int c = 0; c < 16; c++) o_acc[i][c] = 0.f;
    }
    __syncthreads();

    for (int kt = 0; kt <= qt; kt++) {
        const long kbase = qkvbase + (long)(posbase + kt * 64 * r) * DD;
        float sc[4][4];
#pragma unroll
        for (int i = 0; i < 4; i++)
#pragma unroll
            for (int j = 0; j < 4; j++) sc[i][j] = 0.f;

        // S = Q K^T in 8 k-slabs of 32
        for (int k0 = 0; k0 < DD; k0 += 32) {
#pragma unroll
            for (int v = 0; v < 2; v++) {        // 64x32 K slab
                int idx = t + v * 256;
                int row = idx >> 3, c4 = (idx & 7) << 2;
                float4 k4 = *(const float4*)(g_K + kbase + (long)row * r * DD + k0 + c4);
                float* ks = KVs + row * 33 + c4;
                ks[0] = k4.x; ks[1] = k4.y; ks[2] = k4.z; ks[3] = k4.w;
            }
            __syncthreads();
#pragma unroll 8
            for (int kk = 0; kk < 32; kk++) {
                float a[4], b[4];
#pragma unroll
                for (int i = 0; i < 4; i++) a[i] = Qs[(ty + 16 * i) * QS_STRIDE + k0 + kk];
#pragma unroll
                for (int j = 0; j < 4; j++) b[j] = KVs[(tx + 16 * j) * 33 + kk];
#pragma unroll
                for (int i = 0; i < 4; i++)
#pragma unroll
                    for (int j = 0; j < 4; j++) sc[i][j] = fmaf(a[i], b[j], sc[i][j]);
            }
            __syncthreads();
        }

        if (kt == qt) {                          // diagonal tile: causal mask
#pragma unroll
            for (int i = 0; i < 4; i++)
#pragma unroll
                for (int j = 0; j < 4; j++)
                    if (tx + 16 * j > ty + 16 * i) sc[i][j] = -1e30f;
        }

        // online softmax update
        float scale[4];
#pragma unroll
        for (int i = 0; i < 4; i++) {
            float mt = fmaxf(fmaxf(sc[i][0], sc[i][1]), fmaxf(sc[i][2], sc[i][3]));
            mt = rmax16(mt);
            float mnew = fmaxf(m_i[i], mt);
            scale[i] = expf(m_i[i] - mnew);
            m_i[i] = mnew;
            float r0 = 0.f;
#pragma unroll
            for (int j = 0; j < 4; j++) {
                float p = expf(sc[i][j] - mnew);
                Ps[(ty + 16 * i) * PS_STRIDE + tx + 16 * j] = p;
                r0 += p;
            }
            l_i[i] = l_i[i] * scale[i] + rsum16(r0);
        }
#pragma unroll
        for (int i = 0; i < 4; i++)
#pragma unroll
            for (int c = 0; c < 16; c++) o_acc[i][c] *= scale[i];
        __syncthreads();                         // Ps visible, KVs reusable

        // O += P @ V, V streamed in two 32x256 slabs
#pragma unroll
        for (int j0 = 0; j0 < 64; j0 += 32) {
#pragma unroll
            for (int v = 0; v < 8; v++) {
                int idx = t + v * 256;           // 2048 float4
                int row = idx >> 6, c4 = (idx & 63) << 2;
                float4 v4 = *(const float4*)(g_V + kbase + (long)(j0 + row) * r * DD + c4);
                *(float4*)(KVs + row * 256 + c4) = v4;
            }
            __syncthreads();
#pragma unroll 4
            for (int j = 0; j < 32; j++) {
                float pv[4];
#pragma unroll
                for (int i = 0; i < 4; i++) pv[i] = Ps[(ty + 16 * i) * PS_STRIDE + j0 + j];
#pragma unroll
                for (int c = 0; c < 16; c++) {
                    float vv = KVs[j * 256 + tx + 16 * c];
#pragma unroll
                    for (int i = 0; i < 4; i++) o_acc[i][c] = fmaf(pv[i], vv, o_acc[i][c]);
                }
            }
            __syncthreads();
        }
    }

    // epilogue: normalized output + unnormalized denominator
#pragma unroll
    for (int i = 0; i < 4; i++) {
        int row = qt * 64 + ty + 16 * i;
        float inv = 1.0f / l_i[i];
#pragma unroll
        for (int c = 0; c < 16; c++)
            g_O[(s * LSEG + row) * DD + tx + 16 * c] = o_acc[i][c] * inv;
        if (tx == 0) g_den[s * LSEG + row] = l_i[i] * expf(m_i[i]);
    }
}

// ---------------- Phase 3: combine (gather form of scatter-add) ------------
// grid = 32768 (b*8192+p), 64 threads, float4 per thread
__global__ __launch_bounds__(64) void combine_kernel(float* __restrict__ out)
{
    const int bp = blockIdx.x;
    const int b = bp >> 13, p = bp & 8191;

    const int slot0 = (p >> 11) * 4 + b, j0 = p & 2047;
    float d0 = g_den[slot0 * LSEG + j0];
    float sum = d0;
    int slot1 = -1, j1 = 0, slot2 = -1, j2 = 0;
    float d1 = 0.f, d2 = 0.f;
    if ((p & 1) == 0) {
        slot1 = 16 + (p >> 12) * 4 + b; j1 = (p & 4095) >> 1;
        d1 = g_den[slot1 * LSEG + j1]; sum += d1;
    }
    if ((p & 3) == 0) {
        slot2 = 24 + b; j2 = p >> 2;
        d2 = g_den[slot2 * LSEG + j2]; sum += d2;
    }
    const float inv = 1.0f / sum;
    const int c = threadIdx.x << 2;

    float4 o0 = *(const float4*)(g_O + (slot0 * LSEG + j0) * DD + c);
    float a0 = d0 * inv;
    float4 res;
    res.x = o0.x * a0; res.y = o0.y * a0; res.z = o0.z * a0; res.w = o0.w * a0;
    if (slot1 >= 0) {
        float4 o1 = *(const float4*)(g_O + (slot1 * LSEG + j1) * DD + c);
        float a1 = d1 * inv;
        res.x = fmaf(o1.x, a1, res.x); res.y = fmaf(o1.y, a1, res.y);
        res.z = fmaf(o1.z, a1, res.z); res.w = fmaf(o1.w, a1, res.w);
    }
    if (slot2 >= 0) {
        float4 o2 = *(const float4*)(g_O + (slot2 * LSEG + j2) * DD + c);
        float a2 = d2 * inv;
        res.x = fmaf(o2.x, a2, res.x); res.y = fmaf(o2.y, a2, res.y);
        res.z = fmaf(o2.z, a2, res.z); res.w = fmaf(o2.w, a2, res.w);
    }
    *(float4*)(out + ((long)b * NN + p) * DD + c) = res;
}

// ---------------- launch ---------------------------------------------------
extern "C" void kernel_launch(void* const* d_in, const int* in_sizes, int n_in,
                              void* d_out, int out_size)
{
    (void)in_sizes; (void)n_in; (void)out_size;
    const float* x  = (const float*)d_in[0];
    const float* Wq = (const float*)d_in[1];
    const float* Wk = (const float*)d_in[2];
    const float* Wv = (const float*)d_in[3];

    cudaFuncSetAttribute(attn_kernel, cudaFuncAttributeMaxDynamicSharedMemorySize,
                         SMEM_FLOATS * (int)sizeof(float));

    qkv_kernel<<<dim3(512, 4, 3), 256>>>(x, Wq, Wk, Wv);
    attn_kernel<<<dim3(32, 28), 256, SMEM_FLOATS * sizeof(float)>>>();
    combine_kernel<<<32768, 64>>>((float*)d_out);
}

// round 2
// speedup vs baseline: 1.1317x; 1.1317x over previous
#include <cuda_runtime.h>
#include <math.h>

#define BB   4
#define NN   8192
#define CC   256
#define DD   256
#define LSEG 2048
#define NSEG 28

typedef unsigned long long ull;

// ---------------- packed fp32x2 helpers (sm_100+ PTX) ----------------------
__device__ __forceinline__ void ffma2(ull &d, ull a, ull b) {
    asm("fma.rn.f32x2 %0, %1, %2, %0;" : "+l"(d) : "l"(a), "l"(b));
}
__device__ __forceinline__ void fmul2(ull &d, ull s) {
    asm("mul.rn.f32x2 %0, %0, %1;" : "+l"(d) : "l"(s));
}
__device__ __forceinline__ ull bcast2(float x) {
    ull r; asm("mov.b64 %0, {%1, %1};" : "=l"(r) : "f"(x)); return r;
}
__device__ __forceinline__ float2 unpack2(ull v) {
    float2 r; asm("mov.b64 {%0, %1}, %2;" : "=f"(r.x), "=f"(r.y) : "l"(v)); return r;
}

// ---------------- scratch (__device__ globals; no runtime alloc) ----------
__device__ float g_Q[BB * NN * DD];
__device__ float g_K[BB * NN * DD];
__device__ float g_V[BB * NN * DD];
__device__ float g_O[NSEG * LSEG * DD];
__device__ float g_den[NSEG * LSEG];

// ---------------- Phase 1: QKV projection GEMM ----------------------------
// X[32768,256] @ W[256,256] -> {Q,K,V}[32768,256].  grid=(512,4,3), 256 thr.
// Output columns paired: thread owns cols {2tx+32jp, 2tx+32jp+1}, jp in 0..1.
__global__ __launch_bounds__(256) void qkv_kernel(
    const float* __restrict__ X, const float* __restrict__ Wq,
    const float* __restrict__ Wk, const float* __restrict__ Wv)
{
    const float* W   = (blockIdx.z == 0) ? Wq : (blockIdx.z == 1) ? Wk : Wv;
    float*       Out = (blockIdx.z == 0) ? g_Q : (blockIdx.z == 1) ? g_K : g_V;
    const int m0 = blockIdx.x * 64, n0 = blockIdx.y * 64;

    __shared__ float Xs[64 * 33];
    __shared__ float Ws[32 * 68];

    const int t = threadIdx.x, tx = t & 15, ty = t >> 4;
    ull acc2[4][2];
#pragma unroll
    for (int i = 0; i < 4; i++) { acc2[i][0] = 0ull; acc2[i][1] = 0ull; }

    for (int k0 = 0; k0 < CC; k0 += 32) {
#pragma unroll
        for (int v = 0; v < 2; v++) {            // 64x32 X tile
            int idx = t + v * 256;
            int row = idx >> 3, c4 = (idx & 7) << 2;
            float4 x4 = *(const float4*)(X + (long)(m0 + row) * CC + k0 + c4);
            float* xs = Xs + row * 33 + c4;
            xs[0] = x4.x; xs[1] = x4.y; xs[2] = x4.z; xs[3] = x4.w;
        }
#pragma unroll
        for (int v = 0; v < 2; v++) {            // 32x64 W tile (stride 68, 16B aligned)
            int idx = t + v * 256;
            int row = idx >> 4, c4 = (idx & 15) << 2;
            float4 w4 = *(const float4*)(W + (long)(k0 + row) * DD + n0 + c4);
            *(float4*)(Ws + row * 68 + c4) = w4;
        }
        __syncthreads();
#pragma unroll 8
        for (int kk = 0; kk < 32; kk++) {
            ull a2[4], b2[2];
#pragma unroll
            for (int i = 0; i < 4; i++) a2[i] = bcast2(Xs[(ty + 16 * i) * 33 + kk]);
#pragma unroll
            for (int jp = 0; jp < 2; jp++)
                b2[jp] = *(const ull*)(Ws + kk * 68 + 2 * tx + 32 * jp);
#pragma unroll
            for (int i = 0; i < 4; i++)
#pragma unroll
                for (int jp = 0; jp < 2; jp++) ffma2(acc2[i][jp], a2[i], b2[jp]);
        }
        __syncthreads();
    }
#pragma unroll
    for (int i = 0; i < 4; i++)
#pragma unroll
        for (int jp = 0; jp < 2; jp++) {
            float2 u = unpack2(acc2[i][jp]);
            *(float2*)(Out + (long)(m0 + ty + 16 * i) * DD + n0 + 2 * tx + 32 * jp) =
                make_float2(u.x, u.y);
        }
}

// ---------------- Phase 2: per-segment causal flash attention --------------
__device__ __forceinline__ float rmax16(float v) {
#pragma unroll
    for (int o = 8; o > 0; o >>= 1)
        v = fmaxf(v, __shfl_xor_sync(0xffffffffu, v, o, 16));
    return v;
}
__device__ __forceinline__ float rsum16(float v) {
#pragma unroll
    for (int o = 8; o > 0; o >>= 1)
        v += __shfl_xor_sync(0xffffffffu, v, o, 16);
    return v;
}

#define QS_STRIDE 260                        // 1040B rows: 16B aligned
#define PS_STRIDE 65
#define KS_STRIDE 36                         // 144B rows: 16B aligned
#define PS_OFF    (64 * QS_STRIDE)           // 16640 floats
#define KV_OFF    (PS_OFF + 64 * PS_STRIDE)  // 20800 floats
#define SMEM_FLOATS (KV_OFF + 32 * 256)      // 28992 floats = 115968 B

// grid = (32 q-tiles, 28 segments), 256 threads
__global__ __launch_bounds__(256, 1) void attn_kernel()
{
    extern __shared__ float sm[];
    float* Qs  = sm;
    float* Ps  = sm + PS_OFF;
    float* KVs = sm + KV_OFF;

    const int qt = 31 - (int)blockIdx.x;     // heavy (causal-long) tiles first
    const int s  = blockIdx.y;
    int w, r, base;
    if (s < 16)      { w = 2048; r = 1; base = 0;  }
    else if (s < 24) { w = 4096; r = 2; base = 16; }
    else             { w = 8192; r = 4; base = 24; }
    const int local  = s - base;
    const int seg_id = local >> 2, batch = local & 3;
    const long qkvbase = (long)batch * (NN * DD);
    const int  posbase = seg_id * w;

    const int t = threadIdx.x, tx = t & 15, ty = t >> 4;

    // load 64x256 Q tile, pre-scaled by 1/sqrt(D)=1/16 (exact pow2)
#pragma unroll
    for (int v = 0; v < 16; v++) {
        int idx = t + v * 256;
        int row = idx >> 6, c4 = (idx & 63) << 2;
        long g = qkvbase + (long)(posbase + (qt * 64 + row) * r) * DD + c4;
        float4 q4 = *(const float4*)(g_Q + g);
        q4.x *= 0.0625f; q4.y *= 0.0625f; q4.z *= 0.0625f; q4.w *= 0.0625f;
        *(float4*)(Qs + row * QS_STRIDE + c4) = q4;
    }

    float m_i[4], l_i[4];
    ull o2[4][8];                            // packed output cols {2tx+32cp, +1}
#pragma unroll
    for (int i = 0; i < 4; i++) {
        m_i[i] = -1e30f; l_i[i] = 0.f;
#pragma unroll
        for (int cp = 0; cp < 8; cp++) o2[i][cp] = 0ull;
    }
    __syncthreads();

    for (int kt = 0; kt <= qt; kt++) {
        const long kbase = qkvbase + (long)(posbase + kt * 64 * r) * DD;
        ull sc2[4][4];                       // packed over even/odd k
#pragma unroll
        for (int i = 0; i < 4; i++)
#pragma unroll
            for (int j = 0; j < 4; j++) sc2[i][j] = 0ull;

        // S = Q K^T in 8 k-slabs of 32, k paired (both operands k-contiguous)
        for (int k0 = 0; k0 < DD; k0 += 32) {
#pragma unroll
            for (int v = 0; v < 2; v++) {    // 64x32 K slab, stride 36
                int idx = t + v * 256;
                int row = idx >> 3, c4 = (idx & 7) << 2;
                float4 k4 = *(const float4*)(g_K + kbase + (long)row * r * DD + k0 + c4);
                *(float4*)(KVs + row * KS_STRIDE + c4) = k4;
            }
            __syncthreads();
#pragma unroll
            for (int kk = 0; kk < 32; kk += 4) {
                ulonglong2 a2[4], b2[4];
#pragma unroll
                for (int i = 0; i < 4; i++)
                    a2[i] = *(const ulonglong2*)(Qs + (ty + 16 * i) * QS_STRIDE + k0 + kk);
#pragma unroll
                for (int j = 0; j < 4; j++)
                    b2[j] = *(const ulonglong2*)(KVs + (tx + 16 * j) * KS_STRIDE + kk);
#pragma unroll
                for (int i = 0; i < 4; i++)
#pragma unroll
                    for (int j = 0; j < 4; j++) {
                        ffma2(sc2[i][j], a2[i].x, b2[j].x);
                        ffma2(sc2[i][j], a2[i].y, b2[j].y);
                    }
            }
            __syncthreads();
        }

        float sc[4][4];                      // horizontal reduce of packed pairs
#pragma unroll
        for (int i = 0; i < 4; i++)
#pragma unroll
            for (int j = 0; j < 4; j++) {
                float2 u = unpack2(sc2[i][j]);
                sc[i][j] = u.x + u.y;
            }

        if (kt == qt) {                      // diagonal tile: causal mask
#pragma unroll
            for (int i = 0; i < 4; i++)
#pragma unroll
                for (int j = 0; j < 4; j++)
                    if (tx + 16 * j > ty + 16 * i) sc[i][j] = -1e30f;
        }

        // online softmax update
#pragma unroll
        for (int i = 0; i < 4; i++) {
            float mt = fmaxf(fmaxf(sc[i][0], sc[i][1]), fmaxf(sc[i][2], sc[i][3]));
            mt = rmax16(mt);
            float mnew = fmaxf(m_i[i], mt);
            float scale = __expf(m_i[i] - mnew);
            m_i[i] = mnew;
            float r0 = 0.f;
#pragma unroll
            for (int j = 0; j < 4; j++) {
                float p = __expf(sc[i][j] - mnew);
                Ps[(ty + 16 * i) * PS_STRIDE + tx + 16 * j] = p;
                r0 += p;
            }
            l_i[i] = l_i[i] * scale + rsum16(r0);
            ull s2 = bcast2(scale);
#pragma unroll
            for (int cp = 0; cp < 8; cp++) fmul2(o2[i][cp], s2);
        }
        __syncthreads();                     // Ps visible, KVs reusable

        // O += P @ V, V streamed in two 32x256 slabs; output cols paired
#pragma unroll
        for (int j0 = 0; j0 < 64; j0 += 32) {
#pragma unroll
            for (int v = 0; v < 8; v++) {
                int idx = t + v * 256;
                int row = idx >> 6, c4 = (idx & 63) << 2;
                *(float4*)(KVs + row * 256 + c4) =
                    *(const float4*)(g_V + kbase + (long)(j0 + row) * r * DD + c4);
            }
            __syncthreads();
#pragma unroll 4
            for (int j = 0; j < 32; j++) {
                ull pv2[4];
#pragma unroll
                for (int i = 0; i < 4; i++)
                    pv2[i] = bcast2(Ps[(ty + 16 * i) * PS_STRIDE + j0 + j]);
#pragma unroll
                for (int cp = 0; cp < 8; cp++) {
                    ull vv = *(const ull*)(KVs + j * 256 + 2 * tx + 32 * cp);
#pragma unroll
                    for (int i = 0; i < 4; i++) ffma2(o2[i][cp], pv2[i], vv);
                }
            }
            __syncthreads();
        }
    }

    // epilogue: normalized output + unnormalized denominator
#pragma unroll
    for (int i = 0; i < 4; i++) {
        int row = qt * 64 + ty + 16 * i;
        float inv = 1.0f / l_i[i];
#pragma unroll
        for (int cp = 0; cp < 8; cp++) {
            float2 u = unpack2(o2[i][cp]);
            *(float2*)(g_O + (long)(s * LSEG + row) * DD + 2 * tx + 32 * cp) =
                make_float2(u.x * inv, u.y * inv);
        }
        if (tx == 0) g_den[s * LSEG + row] = l_i[i] * __expf(m_i[i]);
    }
}

// ---------------- Phase 3: combine (gather form of scatter-add) ------------
// grid = 8192 blocks x 256 threads; 4 tokens per block, float4 per thread
__global__ __launch_bounds__(256) void combine_kernel(float* __restrict__ out)
{
    const int token = blockIdx.x * 4 + (threadIdx.x >> 6);
    const int lane  = threadIdx.x & 63;
    const int b = token >> 13, p = token & 8191;

    const int slot0 = (p >> 11) * 4 + b, j0 = p & 2047;
    float d0 = g_den[slot0 * LSEG + j0];
    float sum = d0;
    int slot1 = -1, j1 = 0, slot2 = -1, j2 = 0;
    float d1 = 0.f, d2 = 0.f;
    if ((p & 1) == 0) {
        slot1 = 16 + (p >> 12) * 4 + b; j1 = (p & 4095) >> 1;
        d1 = g_den[slot1 * LSEG + j1]; sum += d1;
    }
    if ((p & 3) == 0) {
        slot2 = 24 + b; j2 = p >> 2;
        d2 = g_den[slot2 * LSEG + j2]; sum += d2;
    }
    const float inv = 1.0f / sum;
    const int c = lane << 2;

    float4 o0 = *(const float4*)(g_O + (slot0 * LSEG + j0) * DD + c);
    float a0 = d0 * inv;
    float4 res;
    res.x = o0.x * a0; res.y = o0.y * a0; res.z = o0.z * a0; res.w = o0.w * a0;
    if (slot1 >= 0) {
        float4 o1 = *(const float4*)(g_O + (slot1 * LSEG + j1) * DD + c);
        float a1 = d1 * inv;
        res.x = fmaf(o1.x, a1, res.x); res.y = fmaf(o1.y, a1, res.y);
        res.z = fmaf(o1.z, a1, res.z); res.w = fmaf(o1.w, a1, res.w);
    }
    if (slot2 >= 0) {
        float4 o2v = *(const float4*)(g_O + (slot2 * LSEG + j2) * DD + c);
        float a2 = d2 * inv;
        res.x = fmaf(o2v.x, a2, res.x); res.y = fmaf(o2v.y, a2, res.y);
        res.z = fmaf(o2v.z, a2, res.z); res.w = fmaf(o2v.w, a2, res.w);
    }
    *(float4*)(out + ((long)b * NN + p) * DD + c) = res;
}

// ---------------- launch ---------------------------------------------------
extern "C" void kernel_launch(void* const* d_in, const int* in_sizes, int n_in,
                              void* d_out, int out_size)
{
    (void)in_sizes; (void)n_in; (void)out_size;
    const float* x  = (const float*)d_in[0];
    const float* Wq = (const float*)d_in[1];
    const float* Wk = (const float*)d_in[2];
    const float* Wv = (const float*)d_in[3];

    cudaFuncSetAttribute(attn_kernel, cudaFuncAttributeMaxDynamicSharedMemorySize,
                         SMEM_FLOATS * (int)sizeof(float));

    qkv_kernel<<<dim3(512, 4, 3), 256>>>(x, Wq, Wk, Wv);
    attn_kernel<<<dim3(32, 28), 256, SMEM_FLOATS * sizeof(float)>>>();
    combine_kernel<<<8192, 256>>>((float*)d_out);
}

// round 3
// speedup vs baseline: 1.1377x; 1.0052x over previous
#include <cuda_runtime.h>
#include <math.h>

#define BB   4
#define NN   8192
#define CC   256
#define DD   256
#define LSEG 2048
#define NSEG 28

typedef unsigned long long ull;

// ---------------- packed fp32x2 helpers (sm_100+ PTX) ----------------------
__device__ __forceinline__ void ffma2(ull &d, ull a, ull b) {
    asm("fma.rn.f32x2 %0, %1, %2, %0;" : "+l"(d) : "l"(a), "l"(b));
}
__device__ __forceinline__ void fmul2(ull &d, ull s) {
    asm("mul.rn.f32x2 %0, %0, %1;" : "+l"(d) : "l"(s));
}
__device__ __forceinline__ ull bcast2(float x) {
    ull r; asm("mov.b64 %0, {%1, %1};" : "=l"(r) : "f"(x)); return r;
}
__device__ __forceinline__ float2 unpack2(ull v) {
    float2 r; asm("mov.b64 {%0, %1}, %2;" : "=f"(r.x), "=f"(r.y) : "l"(v)); return r;
}

// ---------------- scratch (__device__ globals; no runtime alloc) ----------
__device__ float g_Q[BB * NN * DD];
__device__ float g_K[BB * NN * DD];
__device__ float g_V[BB * NN * DD];
__device__ float g_O[NSEG * LSEG * DD];
__device__ float g_den[NSEG * LSEG];

// ---------------- Phase 1: QKV projection GEMM ----------------------------
// X[32768,256] @ W[256,256] -> {Q,K,V}[32768,256].  grid=(512,4,3), 256 thr.
// Output columns paired: thread owns cols {2tx+32jp, 2tx+32jp+1}, jp in 0..1.
__global__ __launch_bounds__(256) void qkv_kernel(
    const float* __restrict__ X, const float* __restrict__ Wq,
    const float* __restrict__ Wk, const float* __restrict__ Wv)
{
    const float* W   = (blockIdx.z == 0) ? Wq : (blockIdx.z == 1) ? Wk : Wv;
    float*       Out = (blockIdx.z == 0) ? g_Q : (blockIdx.z == 1) ? g_K : g_V;
    const int m0 = blockIdx.x * 64, n0 = blockIdx.y * 64;

    __shared__ float Xs[64 * 33];
    __shared__ float Ws[32 * 68];

    const int t = threadIdx.x, tx = t & 15, ty = t >> 4;
    ull acc2[4][2];
#pragma unroll
    for (int i = 0; i < 4; i++) { acc2[i][0] = 0ull; acc2[i][1] = 0ull; }

    for (int k0 = 0; k0 < CC; k0 += 32) {
#pragma unroll
        for (int v = 0; v < 2; v++) {            // 64x32 X tile
            int idx = t + v * 256;
            int row = idx >> 3, c4 = (idx & 7) << 2;
            float4 x4 = *(const float4*)(X + (long)(m0 + row) * CC + k0 + c4);
            float* xs = Xs + row * 33 + c4;
            xs[0] = x4.x; xs[1] = x4.y; xs[2] = x4.z; xs[3] = x4.w;
        }
#pragma unroll
        for (int v = 0; v < 2; v++) {            // 32x64 W tile (stride 68, 16B aligned)
            int idx = t + v * 256;
            int row = idx >> 4, c4 = (idx & 15) << 2;
            float4 w4 = *(const float4*)(W + (long)(k0 + row) * DD + n0 + c4);
            *(float4*)(Ws + row * 68 + c4) = w4;
        }
        __syncthreads();
#pragma unroll 8
        for (int kk = 0; kk < 32; kk++) {
            ull a2[4], b2[2];
#pragma unroll
            for (int i = 0; i < 4; i++) a2[i] = bcast2(Xs[(ty + 16 * i) * 33 + kk]);
#pragma unroll
            for (int jp = 0; jp < 2; jp++)
                b2[jp] = *(const ull*)(Ws + kk * 68 + 2 * tx + 32 * jp);
#pragma unroll
            for (int i = 0; i < 4; i++)
#pragma unroll
                for (int jp = 0; jp < 2; jp++) ffma2(acc2[i][jp], a2[i], b2[jp]);
        }
        __syncthreads();
    }
#pragma unroll
    for (int i = 0; i < 4; i++)
#pragma unroll
        for (int jp = 0; jp < 2; jp++) {
            float2 u = unpack2(acc2[i][jp]);
            *(float2*)(Out + (long)(m0 + ty + 16 * i) * DD + n0 + 2 * tx + 32 * jp) =
                make_float2(u.x, u.y);
        }
}

// ---------------- Phase 2: per-segment causal flash attention --------------
__device__ __forceinline__ float rmax16(float v) {
#pragma unroll
    for (int o = 8; o > 0; o >>= 1)
        v = fmaxf(v, __shfl_xor_sync(0xffffffffu, v, o, 16));
    return v;
}
__device__ __forceinline__ float rsum16(float v) {
#pragma unroll
    for (int o = 8; o > 0; o >>= 1)
        v += __shfl_xor_sync(0xffffffffu, v, o, 16);
    return v;
}

#define QS_STRIDE 260                        // 1040B rows: 16B aligned
#define PS_STRIDE 65
#define KS_STRIDE 36                         // 144B rows: 16B aligned
#define PS_OFF    (64 * QS_STRIDE)           // 16640 floats
#define KV_OFF    (PS_OFF + 64 * PS_STRIDE)  // 20800 floats
#define SMEM_FLOATS (KV_OFF + 32 * 256)      // 28992 floats = 115968 B

// grid = (32 q-tiles, 28 segments), 256 threads
__global__ __launch_bounds__(256, 1) void attn_kernel()
{
    extern __shared__ float sm[];
    float* Qs  = sm;
    float* Ps  = sm + PS_OFF;
    float* KVs = sm + KV_OFF;

    const int qt = 31 - (int)blockIdx.x;     // heavy (causal-long) tiles first
    const int s  = blockIdx.y;
    int w, r, base;
    if (s < 16)      { w = 2048; r = 1; base = 0;  }
    else if (s < 24) { w = 4096; r = 2; base = 16; }
    else             { w = 8192; r = 4; base = 24; }
    const int local  = s - base;
    const int seg_id = local >> 2, batch = local & 3;
    const long qkvbase = (long)batch * (NN * DD);
    const int  posbase = seg_id * w;

    const int t = threadIdx.x, tx = t & 15, ty = t >> 4;

    // load 64x256 Q tile, pre-scaled by 1/sqrt(D)=1/16 (exact pow2)
#pragma unroll
    for (int v = 0; v < 16; v++) {
        int idx = t + v * 256;
        int row = idx >> 6, c4 = (idx & 63) << 2;
        long g = qkvbase + (long)(posbase + (qt * 64 + row) * r) * DD + c4;
        float4 q4 = *(const float4*)(g_Q + g);
        q4.x *= 0.0625f; q4.y *= 0.0625f; q4.z *= 0.0625f; q4.w *= 0.0625f;
        *(float4*)(Qs + row * QS_STRIDE + c4) = q4;
    }

    float m_i[4], l_i[4];
    ull o2[4][8];                            // packed output cols {2tx+32cp, +1}
#pragma unroll
    for (int i = 0; i < 4; i++) {
        m_i[i] = -1e30f; l_i[i] = 0.f;
#pragma unroll
        for (int cp = 0; cp < 8; cp++) o2[i][cp] = 0ull;
    }
    __syncthreads();

    for (int kt = 0; kt <= qt; kt++) {
        const long kbase = qkvbase + (long)(posbase + kt * 64 * r) * DD;
        ull sc2[4][4];                       // packed over even/odd k
#pragma unroll
        for (int i = 0; i < 4; i++)
#pragma unroll
            for (int j = 0; j < 4; j++) sc2[i][j] = 0ull;

        // S = Q K^T in 8 k-slabs of 32, k paired (both operands k-contiguous)
        for (int k0 = 0; k0 < DD; k0 += 32) {
#pragma unroll
            for (int v = 0; v < 2; v++) {    // 64x32 K slab, stride 36
                int idx = t + v * 256;
                int row = idx >> 3, c4 = (idx & 7) << 2;
                float4 k4 = *(const float4*)(g_K + kbase + (long)row * r * DD + k0 + c4);
                *(float4*)(KVs + row * KS_STRIDE + c4) = k4;
            }
            __syncthreads();
#pragma unroll
            for (int kk = 0; kk < 32; kk += 4) {
                ulonglong2 a2[4], b2[4];
#pragma unroll
                for (int i = 0; i < 4; i++)
                    a2[i] = *(const ulonglong2*)(Qs + (ty + 16 * i) * QS_STRIDE + k0 + kk);
#pragma unroll
                for (int j = 0; j < 4; j++)
                    b2[j] = *(const ulonglong2*)(KVs + (tx + 16 * j) * KS_STRIDE + kk);
#pragma unroll
                for (int i = 0; i < 4; i++)
#pragma unroll
                    for (int j = 0; j < 4; j++) {
                        ffma2(sc2[i][j], a2[i].x, b2[j].x);
                        ffma2(sc2[i][j], a2[i].y, b2[j].y);
                    }
            }
            __syncthreads();
        }

        float sc[4][4];                      // horizontal reduce of packed pairs
#pragma unroll
        for (int i = 0; i < 4; i++)
#pragma unroll
            for (int j = 0; j < 4; j++) {
                float2 u = unpack2(sc2[i][j]);
                sc[i][j] = u.x + u.y;
            }

        if (kt == qt) {                      // diagonal tile: causal mask
#pragma unroll
            for (int i = 0; i < 4; i++)
#pragma unroll
                for (int j = 0; j < 4; j++)
                    if (tx + 16 * j > ty + 16 * i) sc[i][j] = -1e30f;
        }

        // online softmax update
#pragma unroll
        for (int i = 0; i < 4; i++) {
            float mt = fmaxf(fmaxf(sc[i][0], sc[i][1]), fmaxf(sc[i][2], sc[i][3]));
            mt = rmax16(mt);
            float mnew = fmaxf(m_i[i], mt);
            float scale = __expf(m_i[i] - mnew);
            m_i[i] = mnew;
            float r0 = 0.f;
#pragma unroll
            for (int j = 0; j < 4; j++) {
                float p = __expf(sc[i][j] - mnew);
                Ps[(ty + 16 * i) * PS_STRIDE + tx + 16 * j] = p;
                r0 += p;
            }
            l_i[i] = l_i[i] * scale + rsum16(r0);
            ull s2 = bcast2(scale);
#pragma unroll
            for (int cp = 0; cp < 8; cp++) fmul2(o2[i][cp], s2);
        }
        __syncthreads();                     // Ps visible, KVs reusable

        // O += P @ V, V streamed in two 32x256 slabs; output cols paired
#pragma unroll
        for (int j0 = 0; j0 < 64; j0 += 32) {
#pragma unroll
            for (int v = 0; v < 8; v++) {
                int idx = t + v * 256;
                int row = idx >> 6, c4 = (idx & 63) << 2;
                *(float4*)(KVs + row * 256 + c4) =
                    *(const float4*)(g_V + kbase + (long)(j0 + row) * r * DD + c4);
            }
            __syncthreads();
#pragma unroll 4
            for (int j = 0; j < 32; j++) {
                ull pv2[4];
#pragma unroll
                for (int i = 0; i < 4; i++)
                    pv2[i] = bcast2(Ps[(ty + 16 * i) * PS_STRIDE + j0 + j]);
#pragma unroll
                for (int cp = 0; cp < 8; cp++) {
                    ull vv = *(const ull*)(KVs + j * 256 + 2 * tx + 32 * cp);
#pragma unroll
                    for (int i = 0; i < 4; i++) ffma2(o2[i][cp], pv2[i], vv);
                }
            }
            __syncthreads();
        }
    }

    // epilogue: normalized output + unnormalized denominator
#pragma unroll
    for (int i = 0; i < 4; i++) {
        int row = qt * 64 + ty + 16 * i;
        float inv = 1.0f / l_i[i];
#pragma unroll
        for (int cp = 0; cp < 8; cp++) {
            float2 u = unpack2(o2[i][cp]);
            *(float2*)(g_O + (long)(s * LSEG + row) * DD + 2 * tx + 32 * cp) =
                make_float2(u.x * inv, u.y * inv);
        }
        if (tx == 0) g_den[s * LSEG + row] = l_i[i] * __expf(m_i[i]);
    }
}

// ---------------- Phase 3: combine (gather form of scatter-add) ------------
// grid = 8192 blocks x 256 threads; 4 tokens per block, float4 per thread
__global__ __launch_bounds__(256) void combine_kernel(float* __restrict__ out)
{
    const int token = blockIdx.x * 4 + (threadIdx.x >> 6);
    const int lane  = threadIdx.x & 63;
    const int b = token >> 13, p = token & 8191;

    const int slot0 = (p >> 11) * 4 + b, j0 = p & 2047;
    float d0 = g_den[slot0 * LSEG + j0];
    float sum = d0;
    int slot1 = -1, j1 = 0, slot2 = -1, j2 = 0;
    float d1 = 0.f, d2 = 0.f;
    if ((p & 1) == 0) {
        slot1 = 16 + (p >> 12) * 4 + b; j1 = (p & 4095) >> 1;
        d1 = g_den[slot1 * LSEG + j1]; sum += d1;
    }
    if ((p & 3) == 0) {
        slot2 = 24 + b; j2 = p >> 2;
        d2 = g_den[slot2 * LSEG + j2]; sum += d2;
    }
    const float inv = 1.0f / sum;
    const int c = lane << 2;

    float4 o0 = *(const float4*)(g_O + (slot0 * LSEG + j0) * DD + c);
    float a0 = d0 * inv;
    float4 res;
    res.x = o0.x * a0; res.y = o0.y * a0; res.z = o0.z * a0; res.w = o0.w * a0;
    if (slot1 >= 0) {
        float4 o1 = *(const float4*)(g_O + (slot1 * LSEG + j1) * DD + c);
        float a1 = d1 * inv;
        res.x = fmaf(o1.x, a1, res.x); res.y = fmaf(o1.y, a1, res.y);
        res.z = fmaf(o1.z, a1, res.z); res.w = fmaf(o1.w, a1, res.w);
    }
    if (slot2 >= 0) {
        float4 o2v = *(const float4*)(g_O + (slot2 * LSEG + j2) * DD + c);
        float a2 = d2 * inv;
        res.x = fmaf(o2v.x, a2, res.x); res.y = fmaf(o2v.y, a2, res.y);
        res.z = fmaf(o2v.z, a2, res.z); res.w = fmaf(o2v.w, a2, res.w);
    }
    *(float4*)(out + ((long)b * NN + p) * DD + c) = res;
}

// ---------------- launch ---------------------------------------------------
extern "C" void kernel_launch(void* const* d_in, const int* in_sizes, int n_in,
                              void* d_out, int out_size)
{
    (void)in_sizes; (void)n_in; (void)out_size;
    const float* x  = (const float*)d_in[0];
    const float* Wq = (const float*)d_in[1];
    const float* Wk = (const float*)d_in[2];
    const float* Wv = (const float*)d_in[3];

    cudaFuncSetAttribute(attn_kernel, cudaFuncAttributeMaxDynamicSharedMemorySize,
                         SMEM_FLOATS * (int)sizeof(float));

    qkv_kernel<<<dim3(512, 4, 3), 256>>>(x, Wq, Wk, Wv);
    attn_kernel<<<dim3(32, 28), 256, SMEM_FLOATS * sizeof(float)>>>();
    combine_kernel<<<8192, 256>>>((float*)d_out);
}

// round 4
// speedup vs baseline: 1.1390x; 1.0011x over previous
#include <cuda_runtime.h>
#include <math.h>

#define BB   4
#define NN   8192
#define CC   256
#define DD   256
#define LSEG 2048
#define NSEG 28

typedef unsigned long long ull;

// ---------------- packed fp32x2 helpers (sm_100+ PTX) ----------------------
__device__ __forceinline__ void ffma2(ull &d, ull a, ull b) {
    asm("fma.rn.f32x2 %0, %1, %2, %0;" : "+l"(d) : "l"(a), "l"(b));
}
__device__ __forceinline__ void fmul2(ull &d, ull s) {
    asm("mul.rn.f32x2 %0, %0, %1;" : "+l"(d) : "l"(s));
}
__device__ __forceinline__ ull bcast2(float x) {
    ull r; asm("mov.b64 %0, {%1, %1};" : "=l"(r) : "f"(x)); return r;
}
__device__ __forceinline__ float2 unpack2(ull v) {
    float2 r; asm("mov.b64 {%0, %1}, %2;" : "=f"(r.x), "=f"(r.y) : "l"(v)); return r;
}

// ---------------- scratch (__device__ globals; no runtime alloc) ----------
__device__ float g_Q[BB * NN * DD];
__device__ float g_K[BB * NN * DD];
__device__ float g_V[BB * NN * DD];
__device__ float g_O[NSEG * LSEG * DD];
__device__ float g_den[NSEG * LSEG];

// ---------------- Phase 1: QKV projection GEMM ----------------------------
// X[32768,256] @ W[256,256] -> {Q,K,V}[32768,256].  grid=(512,4,3), 256 thr.
// Output columns paired: thread owns cols {2tx+32jp, 2tx+32jp+1}, jp in 0..1.
__global__ __launch_bounds__(256) void qkv_kernel(
    const float* __restrict__ X, const float* __restrict__ Wq,
    const float* __restrict__ Wk, const float* __restrict__ Wv)
{
    const float* W   = (blockIdx.z == 0) ? Wq : (blockIdx.z == 1) ? Wk : Wv;
    float*       Out = (blockIdx.z == 0) ? g_Q : (blockIdx.z == 1) ? g_K : g_V;
    const int m0 = blockIdx.x * 64, n0 = blockIdx.y * 64;

    __shared__ float Xs[64 * 33];
    __shared__ float Ws[32 * 68];

    const int t = threadIdx.x, tx = t & 15, ty = t >> 4;
    ull acc2[4][2];
#pragma unroll
    for (int i = 0; i < 4; i++) { acc2[i][0] = 0ull; acc2[i][1] = 0ull; }

    for (int k0 = 0; k0 < CC; k0 += 32) {
#pragma unroll
        for (int v = 0; v < 2; v++) {            // 64x32 X tile
            int idx = t + v * 256;
            int row = idx >> 3, c4 = (idx & 7) << 2;
            float4 x4 = *(const float4*)(X + (long)(m0 + row) * CC + k0 + c4);
            float* xs = Xs + row * 33 + c4;
            xs[0] = x4.x; xs[1] = x4.y; xs[2] = x4.z; xs[3] = x4.w;
        }
#pragma unroll
        for (int v = 0; v < 2; v++) {            // 32x64 W tile (stride 68, 16B aligned)
            int idx = t + v * 256;
            int row = idx >> 4, c4 = (idx & 15) << 2;
            float4 w4 = *(const float4*)(W + (long)(k0 + row) * DD + n0 + c4);
            *(float4*)(Ws + row * 68 + c4) = w4;
        }
        __syncthreads();
#pragma unroll 8
        for (int kk = 0; kk < 32; kk++) {
            ull a2[4], b2[2];
#pragma unroll
            for (int i = 0; i < 4; i++) a2[i] = bcast2(Xs[(ty + 16 * i) * 33 + kk]);
#pragma unroll
            for (int jp = 0; jp < 2; jp++)
                b2[jp] = *(const ull*)(Ws + kk * 68 + 2 * tx + 32 * jp);
#pragma unroll
            for (int i = 0; i < 4; i++)
#pragma unroll
                for (int jp = 0; jp < 2; jp++) ffma2(acc2[i][jp], a2[i], b2[jp]);
        }
        __syncthreads();
    }
#pragma unroll
    for (int i = 0; i < 4; i++)
#pragma unroll
        for (int jp = 0; jp < 2; jp++) {
            float2 u = unpack2(acc2[i][jp]);
            *(float2*)(Out + (long)(m0 + ty + 16 * i) * DD + n0 + 2 * tx + 32 * jp) =
                make_float2(u.x, u.y);
        }
}

// ---------------- Phase 2: per-segment causal flash attention --------------
__device__ __forceinline__ float rmax16(float v) {
#pragma unroll
    for (int o = 8; o > 0; o >>= 1)
        v = fmaxf(v, __shfl_xor_sync(0xffffffffu, v, o, 16));
    return v;
}
__device__ __forceinline__ float rsum16(float v) {
#pragma unroll
    for (int o = 8; o > 0; o >>= 1)
        v += __shfl_xor_sync(0xffffffffu, v, o, 16);
    return v;
}

#define QS_STRIDE 260                        // 1040B rows: 16B aligned
#define PS_STRIDE 65
#define KS_STRIDE 36                         // 144B rows: 16B aligned
#define PS_OFF    (64 * QS_STRIDE)           // 16640 floats
#define KV_OFF    (PS_OFF + 64 * PS_STRIDE)  // 20800 floats
#define SMEM_FLOATS (KV_OFF + 32 * 256)      // 28992 floats = 115968 B

// grid = (32 q-tiles, 28 segments), 256 threads
__global__ __launch_bounds__(256, 1) void attn_kernel()
{
    extern __shared__ float sm[];
    float* Qs  = sm;
    float* Ps  = sm + PS_OFF;
    float* KVs = sm + KV_OFF;

    const int qt = 31 - (int)blockIdx.x;     // heavy (causal-long) tiles first
    const int s  = blockIdx.y;
    int w, r, base;
    if (s < 16)      { w = 2048; r = 1; base = 0;  }
    else if (s < 24) { w = 4096; r = 2; base = 16; }
    else             { w = 8192; r = 4; base = 24; }
    const int local  = s - base;
    const int seg_id = local >> 2, batch = local & 3;
    const long qkvbase = (long)batch * (NN * DD);
    const int  posbase = seg_id * w;

    const int t = threadIdx.x, tx = t & 15, ty = t >> 4;

    // load 64x256 Q tile, pre-scaled by 1/sqrt(D)=1/16 (exact pow2)
#pragma unroll
    for (int v = 0; v < 16; v++) {
        int idx = t + v * 256;
        int row = idx >> 6, c4 = (idx & 63) << 2;
        long g = qkvbase + (long)(posbase + (qt * 64 + row) * r) * DD + c4;
        float4 q4 = *(const float4*)(g_Q + g);
        q4.x *= 0.0625f; q4.y *= 0.0625f; q4.z *= 0.0625f; q4.w *= 0.0625f;
        *(float4*)(Qs + row * QS_STRIDE + c4) = q4;
    }

    float m_i[4], l_i[4];
    ull o2[4][8];                            // packed output cols {2tx+32cp, +1}
#pragma unroll
    for (int i = 0; i < 4; i++) {
        m_i[i] = -1e30f; l_i[i] = 0.f;
#pragma unroll
        for (int cp = 0; cp < 8; cp++) o2[i][cp] = 0ull;
    }
    __syncthreads();

    for (int kt = 0; kt <= qt; kt++) {
        const long kbase = qkvbase + (long)(posbase + kt * 64 * r) * DD;
        ull sc2[4][4];                       // packed over even/odd k
#pragma unroll
        for (int i = 0; i < 4; i++)
#pragma unroll
            for (int j = 0; j < 4; j++) sc2[i][j] = 0ull;

        // S = Q K^T in 8 k-slabs of 32, k paired (both operands k-contiguous)
        for (int k0 = 0; k0 < DD; k0 += 32) {
#pragma unroll
            for (int v = 0; v < 2; v++) {    // 64x32 K slab, stride 36
                int idx = t + v * 256;
                int row = idx >> 3, c4 = (idx & 7) << 2;
                float4 k4 = *(const float4*)(g_K + kbase + (long)row * r * DD + k0 + c4);
                *(float4*)(KVs + row * KS_STRIDE + c4) = k4;
            }
            __syncthreads();
#pragma unroll
            for (int kk = 0; kk < 32; kk += 4) {
                ulonglong2 a2[4], b2[4];
#pragma unroll
                for (int i = 0; i < 4; i++)
                    a2[i] = *(const ulonglong2*)(Qs + (ty + 16 * i) * QS_STRIDE + k0 + kk);
#pragma unroll
                for (int j = 0; j < 4; j++)
                    b2[j] = *(const ulonglong2*)(KVs + (tx + 16 * j) * KS_STRIDE + kk);
#pragma unroll
                for (int i = 0; i < 4; i++)
#pragma unroll
                    for (int j = 0; j < 4; j++) {
                        ffma2(sc2[i][j], a2[i].x, b2[j].x);
                        ffma2(sc2[i][j], a2[i].y, b2[j].y);
                    }
            }
            __syncthreads();
        }

        float sc[4][4];                      // horizontal reduce of packed pairs
#pragma unroll
        for (int i = 0; i < 4; i++)
#pragma unroll
            for (int j = 0; j < 4; j++) {
                float2 u = unpack2(sc2[i][j]);
                sc[i][j] = u.x + u.y;
            }

        if (kt == qt) {                      // diagonal tile: causal mask
#pragma unroll
            for (int i = 0; i < 4; i++)
#pragma unroll
                for (int j = 0; j < 4; j++)
                    if (tx + 16 * j > ty + 16 * i) sc[i][j] = -1e30f;
        }

        // online softmax update
#pragma unroll
        for (int i = 0; i < 4; i++) {
            float mt = fmaxf(fmaxf(sc[i][0], sc[i][1]), fmaxf(sc[i][2], sc[i][3]));
            mt = rmax16(mt);
            float mnew = fmaxf(m_i[i], mt);
            float scale = __expf(m_i[i] - mnew);
            m_i[i] = mnew;
            float r0 = 0.f;
#pragma unroll
            for (int j = 0; j < 4; j++) {
                float p = __expf(sc[i][j] - mnew);
                Ps[(ty + 16 * i) * PS_STRIDE + tx + 16 * j] = p;
                r0 += p;
            }
            l_i[i] = l_i[i] * scale + rsum16(r0);
            ull s2 = bcast2(scale);
#pragma unroll
            for (int cp = 0; cp < 8; cp++) fmul2(o2[i][cp], s2);
        }
        __syncthreads();                     // Ps visible, KVs reusable

        // O += P @ V, V streamed in two 32x256 slabs; output cols paired
#pragma unroll
        for (int j0 = 0; j0 < 64; j0 += 32) {
#pragma unroll
            for (int v = 0; v < 8; v++) {
                int idx = t + v * 256;
                int row = idx >> 6, c4 = (idx & 63) << 2;
                *(float4*)(KVs + row * 256 + c4) =
                    *(const float4*)(g_V + kbase + (long)(j0 + row) * r * DD + c4);
            }
            __syncthreads();
#pragma unroll 4
            for (int j = 0; j < 32; j++) {
                ull pv2[4];
#pragma unroll
                for (int i = 0; i < 4; i++)
                    pv2[i] = bcast2(Ps[(ty + 16 * i) * PS_STRIDE + j0 + j]);
#pragma unroll
                for (int cp = 0; cp < 8; cp++) {
                    ull vv = *(const ull*)(KVs + j * 256 + 2 * tx + 32 * cp);
#pragma unroll
                    for (int i = 0; i < 4; i++) ffma2(o2[i][cp], pv2[i], vv);
                }
            }
            __syncthreads();
        }
    }

    // epilogue: normalized output + unnormalized denominator
#pragma unroll
    for (int i = 0; i < 4; i++) {
        int row = qt * 64 + ty + 16 * i;
        float inv = 1.0f / l_i[i];
#pragma unroll
        for (int cp = 0; cp < 8; cp++) {
            float2 u = unpack2(o2[i][cp]);
            *(float2*)(g_O + (long)(s * LSEG + row) * DD + 2 * tx + 32 * cp) =
                make_float2(u.x * inv, u.y * inv);
        }
        if (tx == 0) g_den[s * LSEG + row] = l_i[i] * __expf(m_i[i]);
    }
}

// ---------------- Phase 3: combine (gather form of scatter-add) ------------
// grid = 8192 blocks x 256 threads; 4 tokens per block, float4 per thread
__global__ __launch_bounds__(256) void combine_kernel(float* __restrict__ out)
{
    const int token = blockIdx.x * 4 + (threadIdx.x >> 6);
    const int lane  = threadIdx.x & 63;
    const int b = token >> 13, p = token & 8191;

    const int slot0 = (p >> 11) * 4 + b, j0 = p & 2047;
    float d0 = g_den[slot0 * LSEG + j0];
    float sum = d0;
    int slot1 = -1, j1 = 0, slot2 = -1, j2 = 0;
    float d1 = 0.f, d2 = 0.f;
    if ((p & 1) == 0) {
        slot1 = 16 + (p >> 12) * 4 + b; j1 = (p & 4095) >> 1;
        d1 = g_den[slot1 * LSEG + j1]; sum += d1;
    }
    if ((p & 3) == 0) {
        slot2 = 24 + b; j2 = p >> 2;
        d2 = g_den[slot2 * LSEG + j2]; sum += d2;
    }
    const float inv = 1.0f / sum;
    const int c = lane << 2;

    float4 o0 = *(const float4*)(g_O + (slot0 * LSEG + j0) * DD + c);
    float a0 = d0 * inv;
    float4 res;
    res.x = o0.x * a0; res.y = o0.y * a0; res.z = o0.z * a0; res.w = o0.w * a0;
    if (slot1 >= 0) {
        float4 o1 = *(const float4*)(g_O + (slot1 * LSEG + j1) * DD + c);
        float a1 = d1 * inv;
        res.x = fmaf(o1.x, a1, res.x); res.y = fmaf(o1.y, a1, res.y);
        res.z = fmaf(o1.z, a1, res.z); res.w = fmaf(o1.w, a1, res.w);
    }
    if (slot2 >= 0) {
        float4 o2v = *(const float4*)(g_O + (slot2 * LSEG + j2) * DD + c);
        float a2 = d2 * inv;
        res.x = fmaf(o2v.x, a2, res.x); res.y = fmaf(o2v.y, a2, res.y);
        res.z = fmaf(o2v.z, a2, res.z); res.w = fmaf(o2v.w, a2, res.w);
    }
    *(float4*)(out + ((long)b * NN + p) * DD + c) = res;
}

// ---------------- launch ---------------------------------------------------
extern "C" void kernel_launch(void* const* d_in, const int* in_sizes, int n_in,
                              void* d_out, int out_size)
{
    (void)in_sizes; (void)n_in; (void)out_size;
    const float* x  = (const float*)d_in[0];
    const float* Wq = (const float*)d_in[1];
    const float* Wk = (const float*)d_in[2];
    const float* Wv = (const float*)d_in[3];

    cudaFuncSetAttribute(attn_kernel, cudaFuncAttributeMaxDynamicSharedMemorySize,
                         SMEM_FLOATS * (int)sizeof(float));

    qkv_kernel<<<dim3(512, 4, 3), 256>>>(x, Wq, Wk, Wv);
    attn_kernel<<<dim3(32, 28), 256, SMEM_FLOATS * sizeof(float)>>>();
    combine_kernel<<<8192, 256>>>((float*)d_out);
}